// round 7
// baseline (speedup 1.0000x reference)
#include <cuda_runtime.h>
#include <math.h>

// Problem constants: pred/target are [16,1,256,256] fp32.
#define B 16
#define H 256
#define W 256
#define NPIX (B * H * W)   // 1048576
#define NBLK 512           // 16 batches x 32 row-tiles of 8 rows
#define TROWS 8            // rows per phase-A tile
#define TCOLS 8            // columns per phase-B block
#define GRP 32             // blocks per batch group

// Scratch (device globals — no allocation allowed; zero-init at load).
// g2 transposed [B][W][H] as uint: bits 0..30 = fp32 g^2, bit 31 = pred-edge.
__device__ unsigned int g_g2T[NPIX];
__device__ float        g_part[NBLK];
__device__ unsigned int g_barB[B];   // per-batch monotonic barrier counters
__device__ unsigned int g_tick;      // monotonic completion ticket

// ---------------------------------------------------------------------------
// Per-batch barrier: only the 32 blocks of one batch sync with each other.
// Safe: all 512 blocks co-resident (4 blocks/SM; 512 <= 148*4).
// ---------------------------------------------------------------------------
__device__ __forceinline__ void group_barrier(int grp_id) {
    __syncthreads();
    if (threadIdx.x == 0) {
        __threadfence();
        unsigned int t = atomicAdd(&g_barB[grp_id], 1u);
        unsigned int target = (t / GRP + 1u) * GRP;
        while (*(volatile unsigned int*)&g_barB[grp_id] < target) { __nanosleep(32); }
        __threadfence();
    }
    __syncthreads();
}

// Nearest set-bit distance in a 256-bit mask (8 words), position x.
__device__ __forceinline__ int nearest_dist(const unsigned int* __restrict__ mask, int x) {
    int best = 0x7FFFFFFF;
    const int wx = x >> 5, bit = x & 31;
    unsigned int m = mask[wx] & (0xFFFFFFFFu >> (31 - bit));   // bits <= x
    if (m) {
        best = bit - (31 - __clz(m));
    } else {
        for (int w = wx - 1; w >= 0; --w) {
            unsigned int mm = mask[w];
            if (mm) { best = x - (w * 32 + 31 - __clz(mm)); break; }
        }
    }
    unsigned int m2 = mask[wx] & (0xFFFFFFFFu << bit);         // bits >= x
    if (m2) {
        int d = (__ffs(m2) - 1) - bit;
        if (d < best) best = d;
    } else {
        for (int w = wx + 1; w < 8; ++w) {
            unsigned int mm = mask[w];
            if (mm) { int d = w * 32 + (__ffs(mm) - 1) - x; if (d < best) best = d; break; }
        }
    }
    return best;
}

// ---------------------------------------------------------------------------
// Single fused kernel. grid = 512 blocks x 256 threads.
// Phase A: 8-row tile: edges (bitwise), 1D row distance, transpose-store.
// Per-batch barrier (32 blocks), then
// Phase B: 8 columns of the SAME batch: exact pruned vertical EDT + sum.
// Finalize: last-finished block reduces the 512 partials (fixed order).
// ---------------------------------------------------------------------------
__global__ void __launch_bounds__(256, 4) edge_loss_fused(
        const float* __restrict__ pred,
        const float* __restrict__ targ,
        float* __restrict__ out) {
    const int bid  = blockIdx.x;          // 0..511
    const int tid  = threadIdx.x;         // 0..255
    const int lane = tid & 31;
    const int wid  = tid >> 5;
    const int b    = bid >> 5;            // batch / barrier group

    __shared__ unsigned int mt[TROWS + 2][8], mp[TROWS + 2][8];   // bool masks (+halo)
    __shared__ unsigned int ht[TROWS + 2][8], hp[TROWS + 2][8];   // horizontal 3-AND
    __shared__ unsigned int te[TROWS][8], pemask[TROWS][8];       // edge masks
    __shared__ unsigned int sg2[TROWS][258];                       // g2+flag (padded)
    __shared__ float        craw_f[TCOLS][257];                    // phase-B columns
    __shared__ float        wsum[8];
    __shared__ bool         amlast;

    // ===================== Phase A: rows =====================
    {
        const int y0 = (bid & 31) * TROWS;
        const int ibase = b * (H * W);

        // Front-batched loads: all halo rows into registers first (MLP ~ 20).
        float tv[TROWS + 2], pv[TROWS + 2];
        #pragma unroll
        for (int r = 0; r < TROWS + 2; ++r) {
            int yy = y0 + r - 1;
            bool inb = (yy >= 0) && (yy < H);
            int off = ibase + yy * W + tid;
            tv[r] = inb ? targ[off] : 1.0f;
            pv[r] = inb ? pred[off] : 1.0f;
        }
        #pragma unroll
        for (int r = 0; r < TROWS + 2; ++r) {
            unsigned int mtb = __ballot_sync(0xFFFFFFFFu, tv[r] > 0.5f);
            unsigned int mpb = __ballot_sync(0xFFFFFFFFu, pv[r] > 0.5f);
            if (lane == 0) { mt[r][wid] = mtb; mp[r][wid] = mpb; }
        }
        __syncthreads();

        // Horizontal 3-AND with cross-word carry (OOB column == true).
        if (tid < (TROWS + 2) * 8) {
            int r = tid >> 3, w = tid & 7;
            unsigned int m, lo, hi;
            m  = mt[r][w];
            lo = (w > 0) ? (mt[r][w - 1] >> 31) : 1u;
            hi = (w < 7) ? (mt[r][w + 1] & 1u)  : 1u;
            ht[r][w] = m & ((m << 1) | lo) & ((m >> 1) | (hi << 31));
            m  = mp[r][w];
            lo = (w > 0) ? (mp[r][w - 1] >> 31) : 1u;
            hi = (w < 7) ? (mp[r][w + 1] & 1u)  : 1u;
            hp[r][w] = m & ((m << 1) | lo) & ((m >> 1) | (hi << 31));
        }
        __syncthreads();

        // Edge = center & ~(AND of 3x3 neighborhood).
        if (tid < TROWS * 8) {
            int r = tid >> 3, w = tid & 7;
            unsigned int a9t = ht[r][w] & ht[r + 1][w] & ht[r + 2][w];
            te[r][w] = mt[r + 1][w] & ~a9t;
            unsigned int a9p = hp[r][w] & hp[r + 1][w] & hp[r + 2][w];
            pemask[r][w] = mp[r + 1][w] & ~a9p;
        }
        __syncthreads();

        // Per-pixel 1D row distance; pack g^2 (fp32) + pred-edge flag (bit31).
        #pragma unroll
        for (int r = 0; r < TROWS; ++r) {
            int best = nearest_dist(te[r], tid);
            float g = (best == 0x7FFFFFFF) ? 1e6f : (float)best;
            unsigned int peb = (pemask[r][tid >> 5] >> (tid & 31)) & 1u;
            sg2[r][tid] = __float_as_uint(g * g) | (peb << 31);
        }
        __syncthreads();

        // Transpose store: thread t -> (y = t&7, xi = t>>3); 8 iterations.
        const int ty = tid & 7, txi = tid >> 3;
        #pragma unroll
        for (int p = 0; p < 8; ++p) {
            int x = p * 32 + txi;
            g_g2T[(b * W + x) * H + y0 + ty] = sg2[ty][x];
        }
    }

    group_barrier(b);   // only the 32 blocks of this batch

    // ===================== Phase B: columns =====================
    unsigned int (*craw)[257] = (unsigned int (*)[257])craw_f;
    float acc = 0.0f;
    {
        // Columns bid*8 .. bid*8+7 all belong to batch b = bid>>5.
        const int colbase = bid * TCOLS;
        #pragma unroll
        for (int k = 0; k < TCOLS; ++k) {     // 8 front-batched LDGs per thread
            int idx = tid + k * 256;          // 0..2047
            int c = idx >> 8, y = idx & 255;
            craw[c][y] = g_g2T[(size_t)(colbase + c) * H + y];
        }
        __syncthreads();
        #pragma unroll
        for (int c = 0; c < TCOLS; ++c) {
            unsigned int raw = craw[c][tid];
            if (raw >> 31) {                   // pred-edge pixel
                float d2 = __uint_as_float(raw & 0x7FFFFFFFu);
                for (int r = 1; r < H; ++r) {
                    float rr = (float)(r * r); // exact in fp32 for r <= 255
                    if (rr >= d2) break;
                    int ym = tid - r, yp = tid + r;
                    if (ym >= 0) d2 = fminf(d2, rr + __uint_as_float(craw[c][ym] & 0x7FFFFFFFu));
                    if (yp < H)  d2 = fminf(d2, rr + __uint_as_float(craw[c][yp] & 0x7FFFFFFFu));
                }
                acc += sqrtf(d2);
            }
        }
    }

    // Block reduction (fp32, fixed order -> deterministic).
    #pragma unroll
    for (int o = 16; o; o >>= 1) acc += __shfl_down_sync(0xFFFFFFFFu, acc, o);
    if (lane == 0) wsum[wid] = acc;
    __syncthreads();
    if (tid == 0) {
        float s = wsum[0] + wsum[1] + wsum[2] + wsum[3]
                + wsum[4] + wsum[5] + wsum[6] + wsum[7];
        g_part[bid] = s;
        __threadfence();
        unsigned int t = atomicAdd(&g_tick, 1u);   // monotonic across graph replays
        amlast = ((t % NBLK) == (NBLK - 1));
    }
    __syncthreads();

    // Last-finished block reduces all partials (fixed order -> deterministic).
    if (amlast) {
        float v = g_part[tid] + g_part[tid + 256];
        #pragma unroll
        for (int o = 16; o; o >>= 1) v += __shfl_down_sync(0xFFFFFFFFu, v, o);
        if (lane == 0) wsum[wid] = v;
        __syncthreads();
        if (tid == 0) {
            double s = 0.0;
            #pragma unroll
            for (int i = 0; i < 8; ++i) s += (double)wsum[i];
            out[0] = (float)(s / (double)NPIX);
        }
    }
}

extern "C" void kernel_launch(void* const* d_in, const int* in_sizes, int n_in,
                              void* d_out, int out_size) {
    const float* pred = (const float*)d_in[0];
    const float* targ = (const float*)d_in[1];
    float* out = (float*)d_out;

    edge_loss_fused<<<NBLK, 256>>>(pred, targ, out);
}